// round 1
// baseline (speedup 1.0000x reference)
#include <cuda_runtime.h>

// GEMM: out[m][d] = sum_k x[m][k] * W[k][d]
// M = 8192 (B*S), K = 4096 (V), N = 32 (D), all fp32.
//
// Strategy (round 0 baseline, tuned SIMT):
//  - K split into KS chunks so grid >= #SMs; partials to static device scratch,
//    deterministic second-pass reduction (no float atomics).
//  - W tile (KT x 32 fp32 = 32 KB) staged in smem per block, broadcast LDS.128 reads.
//  - Packed fma.rn.f32x2 (2 FMA/instr) along the D dimension: 16 b64 accumulators
//    cover all 32 outputs; each thread owns 2 rows for W-load reuse.

#define M_TOTAL 8192
#define K_TOTAL 4096
#define N_OUT   32
#define KT      256                 // K tile per block
#define KS      (K_TOTAL / KT)      // 16 K-splits
#define BM      256                 // rows per block (128 thr * 2 rows)
#define NBM     (M_TOTAL / BM)      // 32 m-blocks
#define THREADS 128

// 16 MB static scratch: [KS][M_TOTAL][N_OUT] fp32 partials
__device__ float g_scratch[(size_t)KS * M_TOTAL * N_OUT];

__device__ __forceinline__ void ffma2(unsigned long long &d,
                                      unsigned long long a,
                                      unsigned long long b) {
    // packed 2x fp32 FMA (Blackwell f32x2 pipe; 2 FMA per issue)
    asm("fma.rn.f32x2 %0, %1, %2, %0;" : "+l"(d) : "l"(a), "l"(b));
}

__device__ __forceinline__ unsigned long long pack2(float v) {
    unsigned long long r;
    asm("mov.b64 %0, {%1, %1};" : "=l"(r) : "f"(v));
    return r;
}

__global__ void __launch_bounds__(THREADS)
gemm_kpart_kernel(const float* __restrict__ x, const float* __restrict__ w) {
    __shared__ float Ws[KT * N_OUT];   // 32 KB W tile

    const int tid = threadIdx.x;
    const int bm  = blockIdx.x % NBM;  // which 256-row stripe
    const int ks  = blockIdx.x / NBM;  // which K split
    const int k0  = ks * KT;

    // Cooperative, coalesced load of the W tile (KT*32 floats = 2048 float4)
    {
        const float4* wg  = (const float4*)(w + (size_t)k0 * N_OUT);
        float4*       wsv = (float4*)Ws;
        #pragma unroll
        for (int i = tid; i < KT * N_OUT / 4; i += THREADS)
            wsv[i] = wg[i];
    }
    __syncthreads();

    const int m0 = bm * BM + tid * 2;           // this thread's 2 rows
    const float* xr0 = x + (size_t)m0 * K_TOTAL + k0;
    const float* xr1 = xr0 + K_TOTAL;

    // 16 packed accumulators per row = 32 fp32 outputs (d pairs)
    unsigned long long acc0[16], acc1[16];
    #pragma unroll
    for (int j = 0; j < 16; j++) { acc0[j] = 0ULL; acc1[j] = 0ULL; }

    for (int k = 0; k < KT; k += 4) {
        const float4 a4 = *(const float4*)(xr0 + k);
        const float4 b4 = *(const float4*)(xr1 + k);
        const float* wk = Ws + k * N_OUT;

        #pragma unroll
        for (int j = 0; j < 4; j++) {
            const float av = (j == 0) ? a4.x : (j == 1) ? a4.y : (j == 2) ? a4.z : a4.w;
            const float bv = (j == 0) ? b4.x : (j == 1) ? b4.y : (j == 2) ? b4.z : b4.w;
            const unsigned long long xa = pack2(av);
            const unsigned long long xb = pack2(bv);
            // W row for this k: 32 floats = 8 x 16B broadcast LDS.128
            const ulonglong2* wp = (const ulonglong2*)(wk + j * N_OUT);
            #pragma unroll
            for (int d = 0; d < 8; d++) {
                const ulonglong2 wv = wp[d];
                ffma2(acc0[2 * d],     xa, wv.x);
                ffma2(acc0[2 * d + 1], xa, wv.y);
                ffma2(acc1[2 * d],     xb, wv.x);
                ffma2(acc1[2 * d + 1], xb, wv.y);
            }
        }
    }

    // Each b64 acc holds two fully-summed fp32 outputs (d=2j, 2j+1): store raw.
    unsigned long long* s0 =
        (unsigned long long*)(g_scratch + ((size_t)ks * M_TOTAL + m0) * N_OUT);
    unsigned long long* s1 = s0 + N_OUT / 2;
    #pragma unroll
    for (int j = 0; j < 16; j++) { s0[j] = acc0[j]; s1[j] = acc1[j]; }
}

// Deterministic reduction over the KS partials.
__global__ void __launch_bounds__(256)
reduce_kernel(float* __restrict__ out) {
    const int i = blockIdx.x * blockDim.x + threadIdx.x;  // float4 index
    const int n4 = M_TOTAL * N_OUT / 4;
    if (i >= n4) return;
    const float4* sc = (const float4*)g_scratch;
    float4 s = make_float4(0.f, 0.f, 0.f, 0.f);
    #pragma unroll
    for (int p = 0; p < KS; p++) {
        const float4 v = sc[(size_t)p * n4 + i];
        s.x += v.x; s.y += v.y; s.z += v.z; s.w += v.w;
    }
    ((float4*)out)[i] = s;
}

extern "C" void kernel_launch(void* const* d_in, const int* in_sizes, int n_in,
                              void* d_out, int out_size) {
    const float* x = (const float*)d_in[0];   // [8192, 4096] fp32
    const float* w = (const float*)d_in[1];   // [4096, 32]   fp32
    float* out = (float*)d_out;               // [8192, 32]   fp32

    gemm_kpart_kernel<<<NBM * KS, THREADS>>>(x, w);

    const int n4 = M_TOTAL * N_OUT / 4;       // 65536 float4 outputs
    reduce_kernel<<<(n4 + 255) / 256, 256>>>(out);
}

// round 3
// speedup vs baseline: 1.6321x; 1.6321x over previous
#include <cuda_runtime.h>
#include <cstdint>

// out[m][d] = sum_k x[m][k] * W[k][d];  M=8192, K=4096, N=32, fp32.
//
// bf16x3 split-precision GEMM on the legacy HMMA pipe (mma.sync is baseline
// PTX; tcgen05 is rejected by this harness's sm_103 ptxas target).
//   x -> (hi, lo) bf16; W -> (hi, lo) bf16 pre-packed as B fragments;
//   D += Ahi*Bhi + Ahi*Blo + Alo*Bhi   (fp32 accumulators)
//
// Warp tile: 32 rows x 32 cols. K split 8x -> partials in static scratch,
// deterministic reduce pass. A fragments are built straight from global fp32
// loads (LDG.64 pairs match the m16n8k16 A layout) — no shared memory at all.

#define M_TOTAL 8192
#define K_TOTAL 4096
#define N_OUT   32
#define KSPLIT  8
#define KPER    (K_TOTAL / KSPLIT)    // 512
#define WROWS   32
#define NMW     (M_TOTAL / WROWS)     // 256 m-warps
#define WARPS_CTA 8
#define THREADS  (WARPS_CTA * 32)
#define NCTA    (NMW * KSPLIT / WARPS_CTA)   // 256

__device__ float    g_part[(size_t)KSPLIT * M_TOTAL * N_OUT];   // 8 MB
__device__ uint32_t g_whi[(K_TOTAL / 2) * N_OUT];               // 256 KB
__device__ uint32_t g_wlo[(K_TOTAL / 2) * N_OUT];               // 256 KB

// pack two fp32 -> bf16x2 (f0 in low half) + residual bf16x2
__device__ __forceinline__ void split2(float f0, float f1,
                                       uint32_t& hp, uint32_t& lp) {
    asm("cvt.rn.bf16x2.f32 %0, %1, %2;" : "=r"(hp) : "f"(f1), "f"(f0));
    float h0 = __uint_as_float(hp << 16);
    float h1 = __uint_as_float(hp & 0xffff0000u);
    float g0 = f0 - h0, g1 = f1 - h1;
    asm("cvt.rn.bf16x2.f32 %0, %1, %2;" : "=r"(lp) : "f"(g1), "f"(g0));
}

__device__ __forceinline__ void mma16816(float* d, const uint32_t* a,
                                         uint32_t b0, uint32_t b1) {
    asm volatile(
        "mma.sync.aligned.m16n8k16.row.col.f32.bf16.bf16.f32 "
        "{%0,%1,%2,%3}, {%4,%5,%6,%7}, {%8,%9}, {%0,%1,%2,%3};"
        : "+f"(d[0]), "+f"(d[1]), "+f"(d[2]), "+f"(d[3])
        : "r"(a[0]), "r"(a[1]), "r"(a[2]), "r"(a[3]), "r"(b0), "r"(b1));
}

// ---- W pre-split: g_whi/g_wlo[kp*32+n] = fragment-ready packed bf16x2 ----
__global__ void __launch_bounds__(256)
wsplit_kernel(const float* __restrict__ w) {
    const int idx = blockIdx.x * 256 + threadIdx.x;      // 65536 = 2048 kp * 32 n
    const int kp = idx >> 5, n = idx & 31;
    const float f0 = w[(size_t)(2 * kp) * N_OUT + n];
    const float f1 = w[(size_t)(2 * kp + 1) * N_OUT + n];
    uint32_t hp, lp;
    split2(f0, f1, hp, lp);
    g_whi[idx] = hp;
    g_wlo[idx] = lp;
}

__global__ void __launch_bounds__(THREADS)
gemm_hmma_kernel(const float* __restrict__ x) {
    const int tid  = threadIdx.x;
    const int wid  = tid >> 5, lane = tid & 31;
    const int gw   = blockIdx.x * WARPS_CTA + wid;
    const int mi   = gw & (NMW - 1);
    const int kp   = gw >> 8;                 // NMW = 256
    const int m0   = mi * WROWS;
    const int k0   = kp * KPER;

    const int r = lane >> 2;                  // group id (row / n-col)
    const int c = lane & 3;                   // thread-in-group (k pairs)

    float d[2][4][4];                         // [mtile][ntile][frag]
    #pragma unroll
    for (int i = 0; i < 2; i++)
        #pragma unroll
        for (int j = 0; j < 4; j++)
            #pragma unroll
            for (int q = 0; q < 4; q++) d[i][j][q] = 0.f;

    // per-mtile row bases (rows r and r+8), k offset c*2
    const float* xr[2][2];
    #pragma unroll
    for (int i = 0; i < 2; i++) {
        xr[i][0] = x + (size_t)(m0 + i * 16 + r)     * K_TOTAL + k0 + c * 2;
        xr[i][1] = x + (size_t)(m0 + i * 16 + r + 8) * K_TOTAL + k0 + c * 2;
    }
    const uint32_t* whi = g_whi + ((size_t)(k0 >> 1)) * N_OUT;
    const uint32_t* wlo = g_wlo + ((size_t)(k0 >> 1)) * N_OUT;

    #pragma unroll 2
    for (int kc = 0; kc < KPER; kc += 16) {
        // ---- A fragments: 8 LDG.64 of fp32 pairs -> hi/lo bf16x2 regs ----
        uint32_t ahi[2][4], alo[2][4];
        #pragma unroll
        for (int i = 0; i < 2; i++) {
            const float2 f00 = *(const float2*)(xr[i][0] + kc);      // (r,   2c)
            const float2 f10 = *(const float2*)(xr[i][1] + kc);      // (r+8, 2c)
            const float2 f01 = *(const float2*)(xr[i][0] + kc + 8);  // (r,   2c+8)
            const float2 f11 = *(const float2*)(xr[i][1] + kc + 8);  // (r+8, 2c+8)
            split2(f00.x, f00.y, ahi[i][0], alo[i][0]);
            split2(f10.x, f10.y, ahi[i][1], alo[i][1]);
            split2(f01.x, f01.y, ahi[i][2], alo[i][2]);
            split2(f11.x, f11.y, ahi[i][3], alo[i][3]);
        }
        // ---- B fragments: L1/L2-resident packed loads ----
        const int kq = (kc >> 1) * N_OUT;
        uint32_t bhi[4][2], blo[4][2];
        #pragma unroll
        for (int j = 0; j < 4; j++) {
            const int n = j * 8 + r;
            bhi[j][0] = whi[kq + c * N_OUT + n];
            bhi[j][1] = whi[kq + (c + 4) * N_OUT + n];
            blo[j][0] = wlo[kq + c * N_OUT + n];
            blo[j][1] = wlo[kq + (c + 4) * N_OUT + n];
        }
        // ---- 24 HMMA: hi*hi + hi*lo + lo*hi ----
        #pragma unroll
        for (int i = 0; i < 2; i++)
            #pragma unroll
            for (int j = 0; j < 4; j++) {
                mma16816(d[i][j], ahi[i], bhi[j][0], bhi[j][1]);
                mma16816(d[i][j], ahi[i], blo[j][0], blo[j][1]);
                mma16816(d[i][j], alo[i], bhi[j][0], bhi[j][1]);
            }
    }

    // ---- store partials: thread holds (rows r, r+8) x (cols 2c, 2c+1) ----
    float* base = g_part + ((size_t)kp * M_TOTAL + m0) * N_OUT;
    #pragma unroll
    for (int i = 0; i < 2; i++)
        #pragma unroll
        for (int j = 0; j < 4; j++) {
            const int col = j * 8 + c * 2;
            float* p0 = base + (size_t)(i * 16 + r)     * N_OUT + col;
            float* p1 = base + (size_t)(i * 16 + r + 8) * N_OUT + col;
            *(float2*)p0 = make_float2(d[i][j][0], d[i][j][1]);
            *(float2*)p1 = make_float2(d[i][j][2], d[i][j][3]);
        }
}

__global__ void __launch_bounds__(256)
reduce_kernel(float* __restrict__ out) {
    const int i = blockIdx.x * 256 + threadIdx.x;       // float4 idx, 65536
    const int n4 = M_TOTAL * N_OUT / 4;
    const float4* sc = (const float4*)g_part;
    float4 s = make_float4(0.f, 0.f, 0.f, 0.f);
    #pragma unroll
    for (int p = 0; p < KSPLIT; p++) {
        const float4 v = sc[(size_t)p * n4 + i];
        s.x += v.x; s.y += v.y; s.z += v.z; s.w += v.w;
    }
    ((float4*)out)[i] = s;
}

extern "C" void kernel_launch(void* const* d_in, const int* in_sizes, int n_in,
                              void* d_out, int out_size) {
    const float* x = (const float*)d_in[0];   // [8192, 4096]
    const float* w = (const float*)d_in[1];   // [4096, 32]
    float* out = (float*)d_out;               // [8192, 32]

    wsplit_kernel<<<(K_TOTAL / 2) * N_OUT / 256, 256>>>(w);
    gemm_hmma_kernel<<<NCTA, THREADS>>>(x);
    reduce_kernel<<<M_TOTAL * N_OUT / 4 / 256, 256>>>(out);
}

// round 4
// speedup vs baseline: 1.9631x; 1.2028x over previous
#include <cuda_runtime.h>
#include <cstdint>

// out[m][d] = sum_k x[m][k] * W[k][d];  M=8192, K=4096, N=32, fp32.
//
// bf16x3 split-precision GEMM on mma.sync (baseline PTX; tcgen05 rejected by
// the harness's sm_103 ptxas target).
//   D += Ahi*Bhi + Ahi*Blo + Alo*Bhi  (fp32 accum), rel_err ~5e-6.
//
// R3 changes vs R2 (54.3us):
//  - W split fused into gemm: per-CTA smem table of fragment-ready bf16x2
//    words, XOR-swizzled so fill and fragment reads are bank-conflict-free.
//  - KSPLIT=16, 4 warps/CTA -> 1024 CTAs (better tail + occupancy).
//  - Explicit next-iter register prefetch of A (16 LDG.64 in flight/warp).
//  - Reduce kernel batches all 16 partial loads into regs (MLP=16).

#define M_TOTAL 8192
#define K_TOTAL 4096
#define N_OUT   32
#define KSPLIT  16
#define KPER    (K_TOTAL / KSPLIT)    // 256
#define NIT     (KPER / 16)           // 16 mma k-steps
#define NPAIR   (KPER / 2)            // 128 k-pairs in smem table
#define WARPS_CTA 4
#define THREADS  (WARPS_CTA * 32)
#define MB_ROWS  (WARPS_CTA * 32)     // 128 rows per CTA
#define NMB      (M_TOTAL / MB_ROWS)  // 64
#define NCTA     (NMB * KSPLIT)       // 1024

__device__ float g_part[(size_t)KSPLIT * M_TOTAL * N_OUT];   // 16 MB partials

// pack two fp32 -> bf16x2 (f0 low) + residual bf16x2
__device__ __forceinline__ void split2(float f0, float f1,
                                       uint32_t& hp, uint32_t& lp) {
    asm("cvt.rn.bf16x2.f32 %0, %1, %2;" : "=r"(hp) : "f"(f1), "f"(f0));
    float h0 = __uint_as_float(hp << 16);
    float h1 = __uint_as_float(hp & 0xffff0000u);
    float g0 = f0 - h0, g1 = f1 - h1;
    asm("cvt.rn.bf16x2.f32 %0, %1, %2;" : "=r"(lp) : "f"(g1), "f"(g0));
}

__device__ __forceinline__ void mma16816(float* d, const uint32_t* a,
                                         uint32_t b0, uint32_t b1) {
    asm volatile(
        "mma.sync.aligned.m16n8k16.row.col.f32.bf16.bf16.f32 "
        "{%0,%1,%2,%3}, {%4,%5,%6,%7}, {%8,%9}, {%0,%1,%2,%3};"
        : "+f"(d[0]), "+f"(d[1]), "+f"(d[2]), "+f"(d[3])
        : "r"(a[0]), "r"(a[1]), "r"(a[2]), "r"(a[3]), "r"(b0), "r"(b1));
}

// smem word address for W-fragment (pair, n): bank-conflict-free both ways
__device__ __forceinline__ int baddr(int pair, int n) {
    return pair * 32 + ((n + pair * 8) & 31);
}

__global__ void __launch_bounds__(THREADS)
gemm_hmma_kernel(const float* __restrict__ x, const float* __restrict__ w) {
    __shared__ uint32_t Bhi[NPAIR * 32];   // 16 KB
    __shared__ uint32_t Blo[NPAIR * 32];   // 16 KB

    const int tid  = threadIdx.x;
    const int wid  = tid >> 5, lane = tid & 31;
    const int mb   = blockIdx.x & (NMB - 1);
    const int kp   = blockIdx.x >> 6;             // NMB = 64
    const int k0   = kp * KPER;
    const int m0   = mb * MB_ROWS + wid * 32;

    // ---- build fragment-ready W table in smem (hi/lo bf16x2) ----
    {
        const int pair = tid >> 5;     // warp handles pairs pair, pair+4, ...
        #pragma unroll
        for (int p = pair; p < NPAIR; p += WARPS_CTA) {
            const float f0 = w[(size_t)(k0 + 2 * p)     * N_OUT + lane];
            const float f1 = w[(size_t)(k0 + 2 * p + 1) * N_OUT + lane];
            uint32_t hp, lp;
            split2(f0, f1, hp, lp);
            const int a = baddr(p, lane);
            Bhi[a] = hp;
            Blo[a] = lp;
        }
    }
    __syncthreads();

    const int r = lane >> 2;    // 0..7: row-in-tile / n-group
    const int c = lane & 3;     // 0..3: k-pair within group

    float d[2][4][4];
    #pragma unroll
    for (int i = 0; i < 2; i++)
        #pragma unroll
        for (int j = 0; j < 4; j++)
            #pragma unroll
            for (int q = 0; q < 4; q++) d[i][j][q] = 0.f;

    const float* xr[2][2];
    #pragma unroll
    for (int i = 0; i < 2; i++) {
        xr[i][0] = x + (size_t)(m0 + i * 16 + r)     * K_TOTAL + k0 + c * 2;
        xr[i][1] = x + (size_t)(m0 + i * 16 + r + 8) * K_TOTAL + k0 + c * 2;
    }

    // A prefetch: 8 float2 per 16-k step
    float2 a_nxt[8], a_cur[8];
    #pragma unroll
    for (int i = 0; i < 2; i++) {
        a_nxt[i * 4 + 0] = *(const float2*)(xr[i][0]);
        a_nxt[i * 4 + 1] = *(const float2*)(xr[i][1]);
        a_nxt[i * 4 + 2] = *(const float2*)(xr[i][0] + 8);
        a_nxt[i * 4 + 3] = *(const float2*)(xr[i][1] + 8);
    }

    #pragma unroll 2
    for (int it = 0; it < NIT; it++) {
        #pragma unroll
        for (int q = 0; q < 8; q++) a_cur[q] = a_nxt[q];
        if (it + 1 < NIT) {
            const int kc = (it + 1) * 16;
            #pragma unroll
            for (int i = 0; i < 2; i++) {
                a_nxt[i * 4 + 0] = *(const float2*)(xr[i][0] + kc);
                a_nxt[i * 4 + 1] = *(const float2*)(xr[i][1] + kc);
                a_nxt[i * 4 + 2] = *(const float2*)(xr[i][0] + kc + 8);
                a_nxt[i * 4 + 3] = *(const float2*)(xr[i][1] + kc + 8);
            }
        }
        // B fragments from swizzled smem (conflict-free)
        const int pb = it * 8;
        uint32_t bhi[4][2], blo[4][2];
        #pragma unroll
        for (int j = 0; j < 4; j++) {
            const int n = j * 8 + r;
            const int a0 = baddr(pb + c, n);
            const int a1 = baddr(pb + c + 4, n);
            bhi[j][0] = Bhi[a0];  bhi[j][1] = Bhi[a1];
            blo[j][0] = Blo[a0];  blo[j][1] = Blo[a1];
        }
        // A split
        uint32_t ahi[2][4], alo[2][4];
        #pragma unroll
        for (int i = 0; i < 2; i++)
            #pragma unroll
            for (int q = 0; q < 4; q++)
                split2(a_cur[i * 4 + q].x, a_cur[i * 4 + q].y,
                       ahi[i][q], alo[i][q]);
        // 24 HMMA
        #pragma unroll
        for (int i = 0; i < 2; i++)
            #pragma unroll
            for (int j = 0; j < 4; j++) {
                mma16816(d[i][j], ahi[i], bhi[j][0], bhi[j][1]);
                mma16816(d[i][j], ahi[i], blo[j][0], blo[j][1]);
                mma16816(d[i][j], alo[i], bhi[j][0], bhi[j][1]);
            }
    }

    // ---- partials ----
    float* base = g_part + ((size_t)kp * M_TOTAL + m0) * N_OUT;
    #pragma unroll
    for (int i = 0; i < 2; i++)
        #pragma unroll
        for (int j = 0; j < 4; j++) {
            const int col = j * 8 + c * 2;
            float* p0 = base + (size_t)(i * 16 + r)     * N_OUT + col;
            float* p1 = base + (size_t)(i * 16 + r + 8) * N_OUT + col;
            *(float2*)p0 = make_float2(d[i][j][0], d[i][j][1]);
            *(float2*)p1 = make_float2(d[i][j][2], d[i][j][3]);
        }
}

__global__ void __launch_bounds__(128)
reduce_kernel(float* __restrict__ out) {
    const int i = blockIdx.x * 128 + threadIdx.x;   // float4 idx, 65536
    const int n4 = M_TOTAL * N_OUT / 4;
    const float4* sc = (const float4*)g_part;
    float4 v[KSPLIT];
    #pragma unroll
    for (int p = 0; p < KSPLIT; p++) v[p] = sc[(size_t)p * n4 + i];
    #pragma unroll
    for (int s = KSPLIT / 2; s >= 1; s >>= 1)
        #pragma unroll
        for (int p = 0; p < s; p++) {
            v[p].x += v[p + s].x; v[p].y += v[p + s].y;
            v[p].z += v[p + s].z; v[p].w += v[p + s].w;
        }
    ((float4*)out)[i] = v[0];
}

extern "C" void kernel_launch(void* const* d_in, const int* in_sizes, int n_in,
                              void* d_out, int out_size) {
    const float* x = (const float*)d_in[0];   // [8192, 4096]
    const float* w = (const float*)d_in[1];   // [4096, 32]
    float* out = (float*)d_out;               // [8192, 32]

    gemm_hmma_kernel<<<NCTA, THREADS>>>(x, w);
    reduce_kernel<<<M_TOTAL * N_OUT / 4 / 128, 128>>>(out);
}